// round 1
// baseline (speedup 1.0000x reference)
#include <cuda_runtime.h>
#include <cstdint>

// Problem constants (fixed by the dataset)
#define S_LEN  4096
#define D_SZ   100
#define TD     200      // 2*D
#define NROWS  8192     // fwd rows [0,4096) + bwd rows [4096,8192)
#define NC     6
#define CO     52

// K2 GEMM tiling
#define NDP    112      // d padded to 16*7
#define MB     64       // rows per block
#define VS     201      // v_s row stride (bank-conflict pad)
#define KC     20       // k-chunk (divides 200)

// ---------------- device scratch (statically allocated; no cudaMalloc) ----------------
__device__ float g_V0T[40000 * NDP];                 // 17.9 MB  V0 transposed+padded: [(i*200+j)][d]
__device__ float g_xg[(size_t)NROWS * 400];          // 13.1 MB  input-side gate preacts
__device__ float g_h3[(size_t)NROWS * CO];           //  1.7 MB  conv outputs
__device__ float g_h [(size_t)NROWS * D_SZ];         //  3.3 MB  LSTM hidden outputs
__device__ int   g_L_dev[1];

// ---------------- helpers ----------------
__device__ __forceinline__ float sigf(float x) {
    return __fdividef(1.0f, 1.0f + __expf(-x));
}
__device__ __forceinline__ float tanhfast(float x) {
    // tanh(x) = 2*sigmoid(2x) - 1
    return fmaf(2.0f, sigf(2.0f * x), -1.0f);
}
__device__ __forceinline__ void fma2(unsigned long long& acc, unsigned long long a, unsigned long long b) {
    asm volatile("fma.rn.f32x2 %0, %1, %2, %0;" : "+l"(acc) : "l"(a), "l"(b));
}
__device__ __forceinline__ float2 unpack2(unsigned long long v) {
    float2 r;
    asm("mov.b64 {%0, %1}, %2;" : "=f"(r.x), "=f"(r.y) : "l"(v));
    return r;
}

// ---------------- K0: transpose V0 (d,i,j) -> V0T (ij, d_padded) ----------------
__global__ void k0_transpose(const float* __restrict__ V) {
    const size_t total = 40000ull * NDP;
    for (size_t idx = (size_t)blockIdx.x * blockDim.x + threadIdx.x; idx < total;
         idx += (size_t)gridDim.x * blockDim.x) {
        int k = (int)(idx / NDP);   // k = i*200 + j
        int d = (int)(idx % NDP);
        g_V0T[idx] = (d < D_SZ) ? V[(size_t)d * 40000 + k] : 0.0f;
    }
}

// ---------------- K1: lengths from mask (B=1) ----------------
__global__ void k1_len(const float* __restrict__ mask, int n) {
    __shared__ float red[1024];
    float s = 0.f;
    for (int i = threadIdx.x; i < n; i += 1024) s += mask[i];
    red[threadIdx.x] = s;
    __syncthreads();
    for (int st = 512; st > 0; st >>= 1) {
        if (threadIdx.x < st) red[threadIdx.x] += red[threadIdx.x + st];
        __syncthreads();
    }
    if (threadIdx.x == 0) g_L_dev[0] = (int)(red[0] + 0.5f);
}

// ---------------- K2: parallel phase — bilinear + p + x_gates + conv ----------------
// Block handles 64 rows x all 100 d (padded to 112). Threads (tx=tid%16 over d, ty=tid/16 over rows).
__global__ void __launch_bounds__(256) k2_main(
    const float* __restrict__ U,
    const float* __restrict__ Ww,  const float* __restrict__ Wb,
    const float* __restrict__ Wih, const float* __restrict__ bih, const float* __restrict__ bhh,
    const float* __restrict__ convw, const float* __restrict__ convb)
{
    extern __shared__ float sm[];
    float* v_s = sm;                       // MB*VS
    float* B_s = sm + MB * VS;             // KC*NDP
    float* p_s = B_s + KC * NDP;           // MB*100

    const int tid = threadIdx.x;
    const int tx = tid & 15;
    const int ty = tid >> 4;
    const int r0 = ty * 4;
    const int d0 = tx * 7;

    const int L = g_L_dev[0];
    const int row0 = blockIdx.x * MB;

    // ---- load v (concat(prev, cur)) for 64 rows, with bwd reversal/masking ----
    for (int e = tid; e < MB * TD; e += 256) {
        int rl = e / TD;
        int j  = e % TD;
        int row = row0 + rl;
        int t = row & (S_LEN - 1);
        bool bwd = row >= S_LEN;
        int sbase = (j < D_SZ) ? (t == 0 ? 0 : t - 1) : t;
        int col   = (j < D_SZ) ? j : j - D_SZ;
        float val;
        if (!bwd) {
            val = U[(size_t)sbase * D_SZ + col];
        } else {
            if (sbase < L) {
                int src = L - 1 - sbase;
                src = src < 0 ? 0 : (src > S_LEN - 1 ? S_LEN - 1 : src);
                val = U[(size_t)src * D_SZ + col];
            } else {
                val = 0.0f;
            }
        }
        v_s[rl * VS + j] = val;
    }

    float acc[4][7];
#pragma unroll
    for (int rr = 0; rr < 4; rr++)
#pragma unroll
        for (int dd = 0; dd < 7; dd++) acc[rr][dd] = 0.0f;

    // ---- main GEMM: bilin[r,d] = sum_{i,j} V0[d,i,j] * v[r,i] * v[r,j] ----
    for (int ch = 0; ch < 2000; ch++) {
        const int k0 = ch * KC;       // = i*200 + j0 (KC divides 200 -> i constant in chunk)
        const int i  = k0 / TD;
        const int j0 = k0 % TD;

        __syncthreads();
        for (int u = tid; u < KC * NDP; u += 256)
            B_s[u] = g_V0T[(size_t)k0 * NDP + u];
        __syncthreads();

        float vi[4];
#pragma unroll
        for (int rr = 0; rr < 4; rr++) vi[rr] = v_s[(r0 + rr) * VS + i];

#pragma unroll
        for (int kk = 0; kk < KC; kk++) {
            float a[4];
#pragma unroll
            for (int rr = 0; rr < 4; rr++) {
                float vj = v_s[(r0 + rr) * VS + (j0 + kk)];
                a[rr] = vi[rr] * vj;
            }
            float b[7];
#pragma unroll
            for (int dd = 0; dd < 7; dd++) b[dd] = B_s[kk * NDP + d0 + dd];
#pragma unroll
            for (int rr = 0; rr < 4; rr++)
#pragma unroll
                for (int dd = 0; dd < 7; dd++)
                    acc[rr][dd] = fmaf(a[rr], b[dd], acc[rr][dd]);
        }
    }

    // ---- p = sigmoid(bilin + v @ Ww^T + Wb) ----
#pragma unroll
    for (int rr = 0; rr < 4; rr++) {
        float s[7];
#pragma unroll
        for (int dd = 0; dd < 7; dd++) s[dd] = 0.0f;
        const float* vr = v_s + (r0 + rr) * VS;
        for (int j = 0; j < TD; j++) {
            float vv = vr[j];
#pragma unroll
            for (int dd = 0; dd < 7; dd++) {
                int d = d0 + dd;
                if (d < D_SZ) s[dd] = fmaf(Ww[d * TD + j], vv, s[dd]);
            }
        }
#pragma unroll
        for (int dd = 0; dd < 7; dd++) {
            int d = d0 + dd;
            if (d < D_SZ) {
                float x = acc[rr][dd] + s[dd] + Wb[d];
                p_s[(r0 + rr) * D_SZ + d] = sigf(x);
            }
        }
    }
    __syncthreads();

    // ---- x_gates = p @ Wih^T + b_ih + b_hh ----
    for (int o = tid; o < MB * 400; o += 256) {
        int rl = o / 400;
        int g  = o % 400;
        float a = bih[g] + bhh[g];
        const float4* wr4 = (const float4*)(Wih + (size_t)g * D_SZ);
        const float4* pr4 = (const float4*)(p_s + rl * D_SZ);
#pragma unroll 5
        for (int q = 0; q < 25; q++) {
            float4 w = wr4[q];
            float4 p = pr4[q];
            a = fmaf(w.x, p.x, a);
            a = fmaf(w.y, p.y, a);
            a = fmaf(w.z, p.z, a);
            a = fmaf(w.w, p.w, a);
        }
        g_xg[(size_t)(row0 + rl) * 400 + g] = a;
    }

    // ---- h3 = conv1d(p, k=5, stride=2, pad=4) + conv_b ----
    float cw0 = convw[0], cw1 = convw[1], cw2 = convw[2], cw3 = convw[3], cw4 = convw[4];
    float cb = convb[0];
    for (int o = tid; o < MB * CO; o += 256) {
        int rl = o / CO;
        int oc = o % CO;
        const float* pr = p_s + rl * D_SZ;
        float s = cb;
        int base = 2 * oc - 4;
#pragma unroll
        for (int k = 0; k < 5; k++) {
            int ix = base + k;
            if (ix >= 0 && ix < D_SZ) {
                float w = (k == 0) ? cw0 : (k == 1) ? cw1 : (k == 2) ? cw2 : (k == 3) ? cw3 : cw4;
                s = fmaf(w, pr[ix], s);
            }
        }
        g_h3[(size_t)(row0 + rl) * CO + oc] = s;
    }
}

// ---------------- K3: sequential LSTM over 8192 steps (fwd then bwd, carried state) ----------------
__global__ void __launch_bounds__(416, 1) k3_seq(const float* __restrict__ Whh) {
    __shared__ __align__(16) float h_s[D_SZ];
    __shared__ float act_s[400];
    const int g = threadIdx.x;

    unsigned long long w2[50];
    if (g < 400) {
        const unsigned long long* wp = (const unsigned long long*)(Whh + (size_t)g * D_SZ);
#pragma unroll
        for (int kk = 0; kk < 50; kk++) w2[kk] = wp[kk];
    }
    float c = 0.0f;
    if (g < D_SZ) h_s[g] = 0.0f;
    float xg_next = (g < 400) ? g_xg[g] : 0.0f;
    __syncthreads();

    for (int t = 0; t < NROWS; t++) {
        if (g < 400) {
            float xg_cur = xg_next;
            if (t < NROWS - 1) xg_next = g_xg[(size_t)(t + 1) * 400 + g];

            unsigned long long a0 = 0ull, a1 = 0ull;
            const unsigned long long* hp = (const unsigned long long*)h_s;
#pragma unroll
            for (int kk = 0; kk < 50; kk += 2) {
                fma2(a0, w2[kk],     hp[kk]);
                fma2(a1, w2[kk + 1], hp[kk + 1]);
            }
            float2 u0 = unpack2(a0);
            float2 u1 = unpack2(a1);
            float x = xg_cur + ((u0.x + u0.y) + (u1.x + u1.y));

            float act;
            if (g >= 200 && g < 300) act = tanhfast(x);
            else                      act = sigf(x);
            act_s[g] = act;
        }
        __syncthreads();
        if (g < D_SZ) {
            float ig = act_s[g];
            float fg = act_s[100 + g];
            float gg = act_s[200 + g];
            float og = act_s[300 + g];
            c = fmaf(fg, c, ig * gg);
            float h = og * tanhfast(c);
            h_s[g] = h;
            g_h[(size_t)t * D_SZ + g] = h;
        }
        __syncthreads();
    }
}

// ---------------- K4: logits + log_softmax, with backward reversal ----------------
__global__ void k4_epilogue(const float* __restrict__ Wsw, const float* __restrict__ Wsb,
                            float* __restrict__ out) {
    int t = blockIdx.x * blockDim.x + threadIdx.x;
    if (t >= S_LEN) return;
    const int L = g_L_dev[0];

    float acc[NC];
#pragma unroll
    for (int cc = 0; cc < NC; cc++) acc[cc] = Wsb[cc];

    const float* hf  = g_h  + (size_t)t * D_SZ;
    const float* h3f = g_h3 + (size_t)t * CO;

    for (int j = 0; j < D_SZ; j++) {
        float x = hf[j];
#pragma unroll
        for (int cc = 0; cc < NC; cc++) acc[cc] = fmaf(Wsw[cc * 304 + j], x, acc[cc]);
    }
    for (int j = 0; j < CO; j++) {
        float x = h3f[j];
#pragma unroll
        for (int cc = 0; cc < NC; cc++) acc[cc] = fmaf(Wsw[cc * 304 + 100 + j], x, acc[cc]);
    }

    if (t < L) {
        int sidx = L - 1 - t;
        sidx = sidx < 0 ? 0 : (sidx > S_LEN - 1 ? S_LEN - 1 : sidx);
        const float* hb  = g_h  + (size_t)(S_LEN + sidx) * D_SZ;
        const float* h3b = g_h3 + (size_t)(S_LEN + sidx) * CO;
        for (int j = 0; j < D_SZ; j++) {
            float x = hb[j];
#pragma unroll
            for (int cc = 0; cc < NC; cc++) acc[cc] = fmaf(Wsw[cc * 304 + 152 + j], x, acc[cc]);
        }
        for (int j = 0; j < CO; j++) {
            float x = h3b[j];
#pragma unroll
            for (int cc = 0; cc < NC; cc++) acc[cc] = fmaf(Wsw[cc * 304 + 252 + j], x, acc[cc]);
        }
    }

    float m = acc[0];
#pragma unroll
    for (int cc = 1; cc < NC; cc++) m = fmaxf(m, acc[cc]);
    float s = 0.0f;
#pragma unroll
    for (int cc = 0; cc < NC; cc++) s += __expf(acc[cc] - m);
    float lse = m + logf(s);
#pragma unroll
    for (int cc = 0; cc < NC; cc++) out[(size_t)t * NC + cc] = acc[cc] - lse;
}

// ---------------- launcher ----------------
extern "C" void kernel_launch(void* const* d_in, const int* in_sizes, int n_in,
                              void* d_out, int out_size) {
    const float* U     = (const float*)d_in[0];
    const float* mask  = (const float*)d_in[1];
    const float* V     = (const float*)d_in[2];
    const float* Ww    = (const float*)d_in[3];
    const float* Wb    = (const float*)d_in[4];
    const float* Wsw   = (const float*)d_in[5];
    const float* Wsb   = (const float*)d_in[6];
    const float* Wih   = (const float*)d_in[7];
    const float* Whh   = (const float*)d_in[8];
    const float* bih   = (const float*)d_in[9];
    const float* bhh   = (const float*)d_in[10];
    const float* convw = (const float*)d_in[11];
    const float* convb = (const float*)d_in[12];
    float* out = (float*)d_out;

    const int smem2 = (MB * VS + KC * NDP + MB * D_SZ) * (int)sizeof(float); // 86016 B
    cudaFuncSetAttribute(k2_main, cudaFuncAttributeMaxDynamicSharedMemorySize, smem2);

    k0_transpose<<<2048, 256>>>(V);
    k1_len<<<1, 1024>>>(mask, in_sizes[1]);
    k2_main<<<128, 256, smem2>>>(U, Ww, Wb, Wih, bih, bhh, convw, convb);
    k3_seq<<<1, 416>>>(Whh);
    k4_epilogue<<<32, 128>>>(Wsw, Wsb, out);
}

// round 2
// speedup vs baseline: 1.3342x; 1.3342x over previous
#include <cuda_runtime.h>
#include <cstdint>

// Problem constants (fixed by the dataset)
#define S_LEN  4096
#define D_SZ   100
#define TD     200      // 2*D
#define NROWS  8192     // fwd rows [0,4096) + bwd rows [4096,8192)
#define NC     6
#define CO     52

// K2 GEMM tiling
#define NDP     112     // d padded to 16*7
#define MB      64      // rows per block
#define VS      224     // v_s row stride (padded, zero-filled cols [200,224))
#define KC      20      // k-chunk
#define NCHUNKS 1110    // 1100 symmetric-bilinear chunks + 10 Ww chunks
#define PADK    (NCHUNKS * KC)   // 22200 padded K rows
#define CHELEMS (KC * NDP)       // 2240 floats per chunk

// ---------------- device scratch (statically allocated; no cudaMalloc) ----------------
__device__ float g_V0T[(size_t)PADK * NDP];          // 9.95 MB  packed symmetric V0 (+Ww tail)
__device__ int   g_ck[NCHUNKS];                      // chunk meta: (i<<16) | j0  (i==200 => Ww rows, vi=1)
__device__ float g_xg[(size_t)NROWS * 400];          // 13.1 MB  input-side gate preacts
__device__ float g_h3[(size_t)NROWS * CO];           //  1.7 MB  conv outputs
__device__ float g_h [(size_t)NROWS * D_SZ];         //  3.3 MB  LSTM hidden outputs
__device__ int   g_L_dev[1];

// ---------------- helpers ----------------
__device__ __forceinline__ float sigf(float x) {
    return __fdividef(1.0f, 1.0f + __expf(-x));
}
__device__ __forceinline__ float tanhfast(float x) {
    return fmaf(2.0f, sigf(2.0f * x), -1.0f);
}
__device__ __forceinline__ void fma2(unsigned long long& acc, unsigned long long a, unsigned long long b) {
    asm volatile("fma.rn.f32x2 %0, %1, %2, %0;" : "+l"(acc) : "l"(a), "l"(b));
}
__device__ __forceinline__ unsigned long long add2(unsigned long long a, unsigned long long b) {
    unsigned long long r;
    asm("add.rn.f32x2 %0, %1, %2;" : "=l"(r) : "l"(a), "l"(b));
    return r;
}
__device__ __forceinline__ float2 unpack2(unsigned long long v) {
    float2 r;
    asm("mov.b64 {%0, %1}, %2;" : "=f"(r.x), "=f"(r.y) : "l"(v));
    return r;
}

// ---------------- K_init: chunk metadata (single thread, trivial) ----------------
__global__ void k_init() {
    if (threadIdx.x == 0 && blockIdx.x == 0) {
        int c = 0;
        for (int i = 0; i < TD; i++) {
            int nch = (TD - i + KC - 1) / KC;
            for (int cc = 0; cc < nch; cc++) {
                g_ck[c++] = (i << 16) | (i + cc * KC);
            }
        }
        for (int cc = 0; cc < 10; cc++) {
            g_ck[c++] = (TD << 16) | (cc * KC);   // Ww rows: vi = 1
        }
        // c == 1110 by construction
    }
}

// ---------------- K0: build packed symmetric V0T (+ Ww tail), padded with zeros ----------------
__global__ void k0_fill(const float* __restrict__ V, const float* __restrict__ Ww) {
    const size_t total = (size_t)PADK * NDP;
    for (size_t idx = (size_t)blockIdx.x * blockDim.x + threadIdx.x; idx < total;
         idx += (size_t)gridDim.x * blockDim.x) {
        int row = (int)(idx / NDP);
        int d   = (int)(idx % NDP);
        float val = 0.0f;
        if (d < D_SZ) {
            int ch = row / KC;
            int meta = g_ck[ch];
            int i = meta >> 16;
            int j = (meta & 0xffff) + (row - ch * KC);
            if (i < TD) {
                if (j < TD) {
                    val = V[(size_t)d * 40000 + i * TD + j];
                    if (j > i) val += V[(size_t)d * 40000 + j * TD + i];
                }
            } else {
                val = Ww[d * TD + j];   // j < 200 always for Ww chunks
            }
        }
        g_V0T[idx] = val;
    }
}

// ---------------- K1: lengths from mask (B=1) ----------------
__global__ void k1_len(const float* __restrict__ mask, int n) {
    __shared__ float red[1024];
    float s = 0.f;
    for (int i = threadIdx.x; i < n; i += 1024) s += mask[i];
    red[threadIdx.x] = s;
    __syncthreads();
    for (int st = 512; st > 0; st >>= 1) {
        if (threadIdx.x < st) red[threadIdx.x] += red[threadIdx.x + st];
        __syncthreads();
    }
    if (threadIdx.x == 0) g_L_dev[0] = (int)(red[0] + 0.5f);
}

// ---------------- K2: parallel phase — symmetric bilinear (+Ww folded) + p + x_gates + conv ----------------
__global__ void __launch_bounds__(256) k2_main(
    const float* __restrict__ U,
    const float* __restrict__ Wb,
    const float* __restrict__ Wih, const float* __restrict__ bih, const float* __restrict__ bhh,
    const float* __restrict__ convw, const float* __restrict__ convb)
{
    extern __shared__ float sm[];
    float* v_s = sm;                          // MB*VS = 14336
    float* B_s = sm + MB * VS;                // 2 * CHELEMS = 4480
    float* p_s = B_s + 2 * CHELEMS;           // MB*100 = 6400
    int*  s_ck = (int*)(p_s + MB * D_SZ);     // 1110 ints

    const int tid = threadIdx.x;
    const int tx = tid & 15;
    const int ty = tid >> 4;
    const int r0 = ty * 4;
    const int d0 = tx * 7;

    const int L = g_L_dev[0];
    const int row0 = blockIdx.x * MB;

    // ---- stage chunk metadata ----
    for (int u = tid; u < NCHUNKS; u += 256) s_ck[u] = g_ck[u];

    // ---- load v (concat(prev, cur)) for 64 rows, with bwd reversal/masking; zero-pad cols [200,224) ----
    for (int e = tid; e < MB * VS; e += 256) {
        int rl = e / VS;
        int j  = e % VS;
        float val = 0.0f;
        if (j < TD) {
            int row = row0 + rl;
            int t = row & (S_LEN - 1);
            bool bwd = row >= S_LEN;
            int sbase = (j < D_SZ) ? (t == 0 ? 0 : t - 1) : t;
            int col   = (j < D_SZ) ? j : j - D_SZ;
            if (!bwd) {
                val = U[(size_t)sbase * D_SZ + col];
            } else if (sbase < L) {
                int src = L - 1 - sbase;
                src = src < 0 ? 0 : (src > S_LEN - 1 ? S_LEN - 1 : src);
                val = U[(size_t)src * D_SZ + col];
            }
        }
        v_s[e] = val;
    }

    // ---- prefetch chunk 0 into B_s buffer 0 ----
    float4 pre[3];
    {
        const float4* src = (const float4*)g_V0T;
#pragma unroll
        for (int q = 0; q < 3; q++) {
            int u = tid + q * 256;
            if (u < CHELEMS / 4) pre[q] = src[u];
        }
#pragma unroll
        for (int q = 0; q < 3; q++) {
            int u = tid + q * 256;
            if (u < CHELEMS / 4) ((float4*)B_s)[u] = pre[q];
        }
    }
    __syncthreads();

    float acc[4][7];
#pragma unroll
    for (int rr = 0; rr < 4; rr++)
#pragma unroll
        for (int dd = 0; dd < 7; dd++) acc[rr][dd] = 0.0f;

    // ---- main GEMM over packed symmetric K (double-buffered B) ----
    for (int c = 0; c < NCHUNKS; c++) {
        const float* Bc = B_s + (c & 1) * CHELEMS;

        // issue prefetch LDGs for chunk c+1
        if (c + 1 < NCHUNKS) {
            const float4* src = (const float4*)(g_V0T + (size_t)(c + 1) * CHELEMS);
#pragma unroll
            for (int q = 0; q < 3; q++) {
                int u = tid + q * 256;
                if (u < CHELEMS / 4) pre[q] = src[u];
            }
        }

        const int meta = s_ck[c];
        const int i  = meta >> 16;
        const int j0 = meta & 0xffff;

        float vi[4];
#pragma unroll
        for (int rr = 0; rr < 4; rr++)
            vi[rr] = (i < TD) ? v_s[(r0 + rr) * VS + i] : 1.0f;

#pragma unroll
        for (int kk = 0; kk < KC; kk++) {
            float a[4];
#pragma unroll
            for (int rr = 0; rr < 4; rr++)
                a[rr] = vi[rr] * v_s[(r0 + rr) * VS + (j0 + kk)];
            float b[7];
#pragma unroll
            for (int dd = 0; dd < 7; dd++) b[dd] = Bc[kk * NDP + d0 + dd];
#pragma unroll
            for (int rr = 0; rr < 4; rr++)
#pragma unroll
                for (int dd = 0; dd < 7; dd++)
                    acc[rr][dd] = fmaf(a[rr], b[dd], acc[rr][dd]);
        }

        // store prefetch into the other buffer
        if (c + 1 < NCHUNKS) {
            float4* dst = (float4*)(B_s + ((c + 1) & 1) * CHELEMS);
#pragma unroll
            for (int q = 0; q < 3; q++) {
                int u = tid + q * 256;
                if (u < CHELEMS / 4) dst[u] = pre[q];
            }
        }
        __syncthreads();
    }

    // ---- p = sigmoid(bilin + Ww·v + Wb)  (Ww already folded into acc) ----
#pragma unroll
    for (int rr = 0; rr < 4; rr++) {
#pragma unroll
        for (int dd = 0; dd < 7; dd++) {
            int d = d0 + dd;
            if (d < D_SZ) {
                float x = acc[rr][dd] + Wb[d];
                p_s[(r0 + rr) * D_SZ + d] = sigf(x);
            }
        }
    }
    __syncthreads();

    // ---- x_gates = p @ Wih^T + b_ih + b_hh ----
    for (int o = tid; o < MB * 400; o += 256) {
        int rl = o / 400;
        int g  = o % 400;
        float a = bih[g] + bhh[g];
        const float4* wr4 = (const float4*)(Wih + (size_t)g * D_SZ);
        const float4* pr4 = (const float4*)(p_s + rl * D_SZ);
#pragma unroll 5
        for (int q = 0; q < 25; q++) {
            float4 w = wr4[q];
            float4 p = pr4[q];
            a = fmaf(w.x, p.x, a);
            a = fmaf(w.y, p.y, a);
            a = fmaf(w.z, p.z, a);
            a = fmaf(w.w, p.w, a);
        }
        g_xg[(size_t)(row0 + rl) * 400 + g] = a;
    }

    // ---- h3 = conv1d(p, k=5, stride=2, pad=4) + conv_b ----
    float cw0 = convw[0], cw1 = convw[1], cw2 = convw[2], cw3 = convw[3], cw4 = convw[4];
    float cb = convb[0];
    for (int o = tid; o < MB * CO; o += 256) {
        int rl = o / CO;
        int oc = o % CO;
        const float* pr = p_s + rl * D_SZ;
        float s = cb;
        int base = 2 * oc - 4;
#pragma unroll
        for (int k = 0; k < 5; k++) {
            int ix = base + k;
            if (ix >= 0 && ix < D_SZ) {
                float w = (k == 0) ? cw0 : (k == 1) ? cw1 : (k == 2) ? cw2 : (k == 3) ? cw3 : cw4;
                s = fmaf(w, pr[ix], s);
            }
        }
        g_h3[(size_t)(row0 + rl) * CO + oc] = s;
    }
}

// ---------------- K3: sequential LSTM over 8192 steps (fwd then bwd, carried state) ----------------
__global__ void __launch_bounds__(416, 1) k3_seq(const float* __restrict__ Whh) {
    __shared__ __align__(16) float h_s[D_SZ];
    __shared__ float act_s[400];
    const int g = threadIdx.x;

    unsigned long long w2[50];
    if (g < 400) {
        const unsigned long long* wp = (const unsigned long long*)(Whh + (size_t)g * D_SZ);
#pragma unroll
        for (int kk = 0; kk < 50; kk++) w2[kk] = wp[kk];
    }
    float c = 0.0f;
    if (g < D_SZ) h_s[g] = 0.0f;
    float xg_next = (g < 400) ? g_xg[g] : 0.0f;
    __syncthreads();

    for (int t = 0; t < NROWS; t++) {
        if (g < 400) {
            float xg_cur = xg_next;
            if (t < NROWS - 1) xg_next = g_xg[(size_t)(t + 1) * 400 + g];

            unsigned long long a0 = 0ull, a1 = 0ull, a2 = 0ull, a3 = 0ull;
            const unsigned long long* hp = (const unsigned long long*)h_s;
#pragma unroll
            for (int kk = 0; kk < 48; kk += 4) {
                fma2(a0, w2[kk],     hp[kk]);
                fma2(a1, w2[kk + 1], hp[kk + 1]);
                fma2(a2, w2[kk + 2], hp[kk + 2]);
                fma2(a3, w2[kk + 3], hp[kk + 3]);
            }
            fma2(a0, w2[48], hp[48]);
            fma2(a1, w2[49], hp[49]);
            unsigned long long s01 = add2(a0, a1);
            unsigned long long s23 = add2(a2, a3);
            unsigned long long st  = add2(s01, s23);
            float2 u = unpack2(st);
            float x = xg_cur + (u.x + u.y);

            float act;
            if (g >= 200 && g < 300) act = tanhfast(x);
            else                      act = sigf(x);
            act_s[g] = act;
        }
        __syncthreads();
        if (g < D_SZ) {
            float ig = act_s[g];
            float fg = act_s[100 + g];
            float gg = act_s[200 + g];
            float og = act_s[300 + g];
            c = fmaf(fg, c, ig * gg);
            float h = og * tanhfast(c);
            h_s[g] = h;
            g_h[(size_t)t * D_SZ + g] = h;
        }
        __syncthreads();
    }
}

// ---------------- K4: logits + log_softmax, with backward reversal ----------------
__global__ void k4_epilogue(const float* __restrict__ Wsw, const float* __restrict__ Wsb,
                            float* __restrict__ out) {
    int t = blockIdx.x * blockDim.x + threadIdx.x;
    if (t >= S_LEN) return;
    const int L = g_L_dev[0];

    float acc[NC];
#pragma unroll
    for (int cc = 0; cc < NC; cc++) acc[cc] = Wsb[cc];

    const float* hf  = g_h  + (size_t)t * D_SZ;
    const float* h3f = g_h3 + (size_t)t * CO;

    for (int j = 0; j < D_SZ; j++) {
        float x = hf[j];
#pragma unroll
        for (int cc = 0; cc < NC; cc++) acc[cc] = fmaf(Wsw[cc * 304 + j], x, acc[cc]);
    }
    for (int j = 0; j < CO; j++) {
        float x = h3f[j];
#pragma unroll
        for (int cc = 0; cc < NC; cc++) acc[cc] = fmaf(Wsw[cc * 304 + 100 + j], x, acc[cc]);
    }

    if (t < L) {
        int sidx = L - 1 - t;
        sidx = sidx < 0 ? 0 : (sidx > S_LEN - 1 ? S_LEN - 1 : sidx);
        const float* hb  = g_h  + (size_t)(S_LEN + sidx) * D_SZ;
        const float* h3b = g_h3 + (size_t)(S_LEN + sidx) * CO;
        for (int j = 0; j < D_SZ; j++) {
            float x = hb[j];
#pragma unroll
            for (int cc = 0; cc < NC; cc++) acc[cc] = fmaf(Wsw[cc * 304 + 152 + j], x, acc[cc]);
        }
        for (int j = 0; j < CO; j++) {
            float x = h3b[j];
#pragma unroll
            for (int cc = 0; cc < NC; cc++) acc[cc] = fmaf(Wsw[cc * 304 + 252 + j], x, acc[cc]);
        }
    }

    float m = acc[0];
#pragma unroll
    for (int cc = 1; cc < NC; cc++) m = fmaxf(m, acc[cc]);
    float s = 0.0f;
#pragma unroll
    for (int cc = 0; cc < NC; cc++) s += __expf(acc[cc] - m);
    float lse = m + logf(s);
#pragma unroll
    for (int cc = 0; cc < NC; cc++) out[(size_t)t * NC + cc] = acc[cc] - lse;
}

// ---------------- launcher ----------------
extern "C" void kernel_launch(void* const* d_in, const int* in_sizes, int n_in,
                              void* d_out, int out_size) {
    const float* U     = (const float*)d_in[0];
    const float* mask  = (const float*)d_in[1];
    const float* V     = (const float*)d_in[2];
    const float* Ww    = (const float*)d_in[3];
    const float* Wb    = (const float*)d_in[4];
    const float* Wsw   = (const float*)d_in[5];
    const float* Wsb   = (const float*)d_in[6];
    const float* Wih   = (const float*)d_in[7];
    const float* Whh   = (const float*)d_in[8];
    const float* bih   = (const float*)d_in[9];
    const float* bhh   = (const float*)d_in[10];
    const float* convw = (const float*)d_in[11];
    const float* convb = (const float*)d_in[12];
    float* out = (float*)d_out;

    const int smem2 = (MB * VS + 2 * CHELEMS + MB * D_SZ) * (int)sizeof(float)
                    + NCHUNKS * (int)sizeof(int);   // ~105 KB
    cudaFuncSetAttribute(k2_main, cudaFuncAttributeMaxDynamicSharedMemorySize, smem2);

    k_init<<<1, 32>>>();
    k0_fill<<<2048, 256>>>(V, Ww);
    k1_len<<<1, 1024>>>(mask, in_sizes[1]);
    k2_main<<<128, 256, smem2>>>(U, Wb, Wih, bih, bhh, convw, convb);
    k3_seq<<<1, 416>>>(Whh);
    k4_epilogue<<<32, 128>>>(Wsw, Wsb, out);
}

// round 6
// speedup vs baseline: 1.3455x; 1.0085x over previous
#include <cuda_runtime.h>
#include <cstdint>

// Problem constants
#define S_LEN  4096
#define D_SZ   100
#define TD     200
#define NROWS  8192
#define NC     6
#define CO     52

// K2 tiling
#define NDP     128                  // d padded to 128 (f32x2 pairs)
#define MB      16                   // rows per tile
#define NTILES  (NROWS / MB)         // 512
#define VS      224                  // v_s row stride
#define KC      20
#define NCHUNKS 1110                 // 1100 symmetric + 10 Ww chunks
#define PADK    (NCHUNKS * KC)       // 22200
#define CHELEMS (KC * NDP)           // 2560
#define NPROD   146                  // producer blocks; block NPROD is the consumer
#define NTHR    416

typedef unsigned long long u64;

// ---------------- device scratch ----------------
__device__ float g_V0T[(size_t)PADK * NDP];     // 11.4 MB packed symmetric V0 (+Ww tail)
__device__ int   g_ck[NCHUNKS];
__device__ float g_xg[(size_t)NROWS * 400];
__device__ float g_h3[(size_t)NROWS * CO];
__device__ float g_h [(size_t)NROWS * D_SZ];
__device__ int   g_L_dev[1];
__device__ int   g_flag[NTILES];
__device__ int   g_ctr[1];

// ---------------- helpers ----------------
__device__ __forceinline__ float sigf(float x) {
    return __fdividef(1.0f, 1.0f + __expf(-x));
}
__device__ __forceinline__ float tanhfast(float x) {
    return fmaf(2.0f, sigf(2.0f * x), -1.0f);
}
__device__ __forceinline__ void fma2(u64& acc, u64 a, u64 b) {
    asm volatile("fma.rn.f32x2 %0, %1, %2, %0;" : "+l"(acc) : "l"(a), "l"(b));
}
__device__ __forceinline__ u64 dup2(float x) {
    u64 r;
    asm("mov.b64 %0, {%1, %1};" : "=l"(r) : "f"(x));
    return r;
}
__device__ __forceinline__ float2 unpack2(u64 v) {
    float2 r;
    asm("mov.b64 {%0, %1}, %2;" : "=f"(r.x), "=f"(r.y) : "l"(v));
    return r;
}

// ---------------- K_init: chunk metadata ----------------
__global__ void k_init() {
    if (threadIdx.x == 0 && blockIdx.x == 0) {
        int c = 0;
        for (int i = 0; i < TD; i++) {
            int nch = (TD - i + KC - 1) / KC;
            for (int cc = 0; cc < nch; cc++) g_ck[c++] = (i << 16) | (i + cc * KC);
        }
        for (int cc = 0; cc < 10; cc++) g_ck[c++] = (TD << 16) | (cc * KC);
    }
}

// ---------------- K0: build packed symmetric V0T (+ Ww tail) ----------------
__global__ void k0_fill(const float* __restrict__ V, const float* __restrict__ Ww) {
    const size_t total = (size_t)PADK * NDP;
    for (size_t idx = (size_t)blockIdx.x * blockDim.x + threadIdx.x; idx < total;
         idx += (size_t)gridDim.x * blockDim.x) {
        int row = (int)(idx / NDP);
        int d   = (int)(idx % NDP);
        float val = 0.0f;
        if (d < D_SZ) {
            int ch = row / KC;
            int meta = g_ck[ch];
            int i = meta >> 16;
            int j = (meta & 0xffff) + (row - ch * KC);
            if (i < TD) {
                if (j < TD) {
                    val = V[(size_t)d * 40000 + i * TD + j];
                    if (j > i) val += V[(size_t)d * 40000 + j * TD + i];
                }
            } else {
                val = Ww[d * TD + j];
            }
        }
        g_V0T[idx] = val;
    }
}

// ---------------- K1: lengths + reset flags/counter ----------------
__global__ void k1_len(const float* __restrict__ mask, int n) {
    __shared__ float red[1024];
    float s = 0.f;
    for (int i = threadIdx.x; i < n; i += 1024) s += mask[i];
    red[threadIdx.x] = s;
    __syncthreads();
    for (int st = 512; st > 0; st >>= 1) {
        if (threadIdx.x < st) red[threadIdx.x] += red[threadIdx.x + st];
        __syncthreads();
    }
    if (threadIdx.x == 0) {
        g_L_dev[0] = (int)(red[0] + 0.5f);
        g_ctr[0] = 0;
    }
    for (int i = threadIdx.x; i < NTILES; i += 1024) g_flag[i] = 0;
}

// ============================================================================
// Fused persistent kernel: blocks 0..NPROD-1 = producers (bilinear GEMM +
// p + x_gates + conv, publish per-tile flags); block NPROD = LSTM consumer
// (spins on flags). Single launch -> all 147 blocks co-resident (<=148 SMs,
// 1 block/SM), so the producer->consumer dependency is safe under plain
// execution, graph replay, AND ncu kernel serialization.
// ============================================================================
__global__ void __launch_bounds__(NTHR, 1) k23_fused(
    const float* __restrict__ U,
    const float* __restrict__ Wb,
    const float* __restrict__ Wih, const float* __restrict__ bih, const float* __restrict__ bhh,
    const float* __restrict__ convw, const float* __restrict__ convb,
    const float* __restrict__ Whh)
{
    const int tid = threadIdx.x;

    if (blockIdx.x < NPROD) {
        // ======================= PRODUCER =======================
        extern __shared__ float sm[];
        float* v_s = sm;                               // MB*VS = 3584 floats
        float* B_s = sm + MB * VS;                     // 2*CHELEMS = 5120 floats
        float* p_s = B_s + 2 * CHELEMS;                // MB*100 = 1600 floats
        int*  s_ck = (int*)(p_s + MB * D_SZ);          // 1110 ints
        __shared__ int s_tile;

        const int tx = tid & 15;        // (for tid<128) d group: 8 floats = 2 ulonglong2
        const int ty = tid >> 4;        // (for tid<128) 0..7 -> 2 rows each
        const int r0 = ty * 2;
        const int d0 = tx * 8;

        const int L = g_L_dev[0];

        for (int u = tid; u < NCHUNKS; u += NTHR) s_ck[u] = g_ck[u];
        __syncthreads();

        while (true) {
            if (tid == 0) s_tile = atomicAdd(g_ctr, 1);
            __syncthreads();
            const int tile = s_tile;
            __syncthreads();
            if (tile >= NTILES) break;
            const int row0 = tile * MB;

            // ---- load v (concat(prev, cur)) for 16 rows ----
            for (int e = tid; e < MB * VS; e += NTHR) {
                int rl = e / VS;
                int j  = e % VS;
                float val = 0.0f;
                if (j < TD) {
                    int row = row0 + rl;
                    int t = row & (S_LEN - 1);
                    bool bwd = row >= S_LEN;
                    int sbase = (j < D_SZ) ? (t == 0 ? 0 : t - 1) : t;
                    int col   = (j < D_SZ) ? j : j - D_SZ;
                    if (!bwd) {
                        val = U[(size_t)sbase * D_SZ + col];
                    } else if (sbase < L) {
                        int src = L - 1 - sbase;
                        src = src < 0 ? 0 : (src > S_LEN - 1 ? S_LEN - 1 : src);
                        val = U[(size_t)src * D_SZ + col];
                    }
                }
                v_s[e] = val;
            }

            // ---- prefetch chunk 0 (all threads; CHELEMS/4 = 640 float4) ----
            float4 pre[2];
#pragma unroll
            for (int q = 0; q < 2; q++) {
                int u = tid + q * NTHR;
                if (u < CHELEMS / 4) pre[q] = ((const float4*)g_V0T)[u];
            }
#pragma unroll
            for (int q = 0; q < 2; q++) {
                int u = tid + q * NTHR;
                if (u < CHELEMS / 4) ((float4*)B_s)[u] = pre[q];
            }
            __syncthreads();

            u64 acc00 = 0, acc01 = 0, acc02 = 0, acc03 = 0;
            u64 acc10 = 0, acc11 = 0, acc12 = 0, acc13 = 0;

            for (int c = 0; c < NCHUNKS; c++) {
                const float* Bc = B_s + (c & 1) * CHELEMS;

                if (c + 1 < NCHUNKS) {
                    const float4* src = (const float4*)(g_V0T + (size_t)(c + 1) * CHELEMS);
#pragma unroll
                    for (int q = 0; q < 2; q++) {
                        int u = tid + q * NTHR;
                        if (u < CHELEMS / 4) pre[q] = src[u];
                    }
                }

                if (tid < 128) {
                    const int meta = s_ck[c];
                    const int i  = meta >> 16;
                    const int j0 = meta & 0xffff;

                    const float vi0 = (i < TD) ? v_s[r0 * VS + i] : 1.0f;
                    const float vi1 = (i < TD) ? v_s[(r0 + 1) * VS + i] : 1.0f;
                    // Each k-row of B is NDP=128 floats = 32 ulonglong2. Thread
                    // covers 8 floats (2 ulonglong2) at float offset d0 = tx*8.
                    const ulonglong2* bp = (const ulonglong2*)Bc + tx * 2;

#pragma unroll
                    for (int kk = 0; kk < KC; kk++) {
                        float vj0 = v_s[r0 * VS + j0 + kk];
                        float vj1 = v_s[(r0 + 1) * VS + j0 + kk];
                        u64 a0 = dup2(vi0 * vj0);
                        u64 a1 = dup2(vi1 * vj1);
                        ulonglong2 b01 = bp[kk * 32];        // row stride = 32 ulonglong2
                        ulonglong2 b23 = bp[kk * 32 + 1];
                        fma2(acc00, a0, b01.x); fma2(acc01, a0, b01.y);
                        fma2(acc02, a0, b23.x); fma2(acc03, a0, b23.y);
                        fma2(acc10, a1, b01.x); fma2(acc11, a1, b01.y);
                        fma2(acc12, a1, b23.x); fma2(acc13, a1, b23.y);
                    }
                }

                if (c + 1 < NCHUNKS) {
                    float4* dst = (float4*)(B_s + ((c + 1) & 1) * CHELEMS);
#pragma unroll
                    for (int q = 0; q < 2; q++) {
                        int u = tid + q * NTHR;
                        if (u < CHELEMS / 4) dst[u] = pre[q];
                    }
                }
                __syncthreads();
            }

            // ---- p = sigmoid(acc + Wb) ----
            if (tid < 128) {
                u64 accs[2][4] = {{acc00, acc01, acc02, acc03}, {acc10, acc11, acc12, acc13}};
#pragma unroll
                for (int rr = 0; rr < 2; rr++) {
#pragma unroll
                    for (int q = 0; q < 4; q++) {
                        float2 v2 = unpack2(accs[rr][q]);
                        int d = d0 + 2 * q;
                        if (d < D_SZ)     p_s[(r0 + rr) * D_SZ + d]     = sigf(v2.x + Wb[d]);
                        if (d + 1 < D_SZ) p_s[(r0 + rr) * D_SZ + d + 1] = sigf(v2.y + Wb[d + 1]);
                    }
                }
            }
            __syncthreads();

            // ---- x_gates = p @ Wih^T + b_ih + b_hh ----
            for (int o = tid; o < MB * 400; o += NTHR) {
                int rl = o / 400;
                int g  = o % 400;
                float a = bih[g] + bhh[g];
                const float4* wr4 = (const float4*)(Wih + (size_t)g * D_SZ);
                const float4* pr4 = (const float4*)(p_s + rl * D_SZ);
#pragma unroll 5
                for (int q = 0; q < 25; q++) {
                    float4 w = wr4[q];
                    float4 p = pr4[q];
                    a = fmaf(w.x, p.x, a);
                    a = fmaf(w.y, p.y, a);
                    a = fmaf(w.z, p.z, a);
                    a = fmaf(w.w, p.w, a);
                }
                g_xg[(size_t)(row0 + rl) * 400 + g] = a;
            }

            // ---- h3 = conv1d(p) ----
            float cw0 = convw[0], cw1 = convw[1], cw2 = convw[2], cw3 = convw[3], cw4 = convw[4];
            float cb = convb[0];
            for (int o = tid; o < MB * CO; o += NTHR) {
                int rl = o / CO;
                int oc = o % CO;
                const float* pr = p_s + rl * D_SZ;
                float s = cb;
                int base = 2 * oc - 4;
#pragma unroll
                for (int k = 0; k < 5; k++) {
                    int ix = base + k;
                    if (ix >= 0 && ix < D_SZ) {
                        float w = (k == 0) ? cw0 : (k == 1) ? cw1 : (k == 2) ? cw2 : (k == 3) ? cw3 : cw4;
                        s = fmaf(w, pr[ix], s);
                    }
                }
                g_h3[(size_t)(row0 + rl) * CO + oc] = s;
            }

            // ---- publish tile ----
            __syncthreads();
            __threadfence();
            if (tid == 0) atomicExch(&g_flag[tile], 1);
            __syncthreads();
        }
    } else {
        // ======================= CONSUMER (LSTM) =======================
        __shared__ __align__(16) float h_s[D_SZ];
        __shared__ float act_s[400];
        const int g = tid;

        u64 w2[50];
        if (g < 400) {
            const u64* wp = (const u64*)(Whh + (size_t)g * D_SZ);
#pragma unroll
            for (int kk = 0; kk < 50; kk++) w2[kk] = wp[kk];
        }
        float c = 0.0f;
        if (g < D_SZ) h_s[g] = 0.0f;
        __syncthreads();

        for (int tile = 0; tile < NTILES; tile++) {
            if (g == 0) {
                while (atomicAdd(&g_flag[tile], 0) == 0) __nanosleep(128);
                __threadfence();
            }
            __syncthreads();

            float xg_cur = (g < 400) ? g_xg[(size_t)tile * MB * 400 + g] : 0.0f;

            for (int tt = 0; tt < MB; tt++) {
                const int t = tile * MB + tt;
                float xg_next = 0.0f;
                if (g < 400 && tt < MB - 1) xg_next = g_xg[(size_t)(t + 1) * 400 + g];

                if (g < 400) {
                    u64 a0 = 0ull, a1 = 0ull, a2 = 0ull, a3 = 0ull;
                    const ulonglong2* hp2 = (const ulonglong2*)h_s;
#pragma unroll
                    for (int q = 0; q < 24; q += 2) {
                        ulonglong2 h01 = hp2[q];
                        ulonglong2 h23 = hp2[q + 1];
                        fma2(a0, w2[2 * q],     h01.x);
                        fma2(a1, w2[2 * q + 1], h01.y);
                        fma2(a2, w2[2 * q + 2], h23.x);
                        fma2(a3, w2[2 * q + 3], h23.y);
                    }
                    {
                        ulonglong2 h01 = hp2[24];
                        fma2(a0, w2[48], h01.x);
                        fma2(a1, w2[49], h01.y);
                    }
                    u64 s01, s23, st;
                    asm("add.rn.f32x2 %0, %1, %2;" : "=l"(s01) : "l"(a0), "l"(a1));
                    asm("add.rn.f32x2 %0, %1, %2;" : "=l"(s23) : "l"(a2), "l"(a3));
                    asm("add.rn.f32x2 %0, %1, %2;" : "=l"(st)  : "l"(s01), "l"(s23));
                    float2 u = unpack2(st);
                    float x = xg_cur + (u.x + u.y);

                    float act;
                    if (g >= 200 && g < 300) act = tanhfast(x);
                    else                     act = sigf(x);
                    act_s[g] = act;
                }
                __syncthreads();
                if (g < D_SZ) {
                    float ig = act_s[g];
                    float fg = act_s[100 + g];
                    float gg = act_s[200 + g];
                    float og = act_s[300 + g];
                    c = fmaf(fg, c, ig * gg);
                    float h = og * tanhfast(c);
                    h_s[g] = h;
                    g_h[(size_t)t * D_SZ + g] = h;
                }
                __syncthreads();
                xg_cur = xg_next;
            }
        }
    }
}

// ---------------- K4: logits + log_softmax ----------------
__global__ void k4_epilogue(const float* __restrict__ Wsw, const float* __restrict__ Wsb,
                            float* __restrict__ out) {
    int t = blockIdx.x * blockDim.x + threadIdx.x;
    if (t >= S_LEN) return;
    const int L = g_L_dev[0];

    float acc[NC];
#pragma unroll
    for (int cc = 0; cc < NC; cc++) acc[cc] = Wsb[cc];

    const float* hf  = g_h  + (size_t)t * D_SZ;
    const float* h3f = g_h3 + (size_t)t * CO;

    for (int j = 0; j < D_SZ; j++) {
        float x = hf[j];
#pragma unroll
        for (int cc = 0; cc < NC; cc++) acc[cc] = fmaf(Wsw[cc * 304 + j], x, acc[cc]);
    }
    for (int j = 0; j < CO; j++) {
        float x = h3f[j];
#pragma unroll
        for (int cc = 0; cc < NC; cc++) acc[cc] = fmaf(Wsw[cc * 304 + 100 + j], x, acc[cc]);
    }

    if (t < L) {
        int sidx = L - 1 - t;
        sidx = sidx < 0 ? 0 : (sidx > S_LEN - 1 ? S_LEN - 1 : sidx);
        const float* hb  = g_h  + (size_t)(S_LEN + sidx) * D_SZ;
        const float* h3b = g_h3 + (size_t)(S_LEN + sidx) * CO;
        for (int j = 0; j < D_SZ; j++) {
            float x = hb[j];
#pragma unroll
            for (int cc = 0; cc < NC; cc++) acc[cc] = fmaf(Wsw[cc * 304 + 152 + j], x, acc[cc]);
        }
        for (int j = 0; j < CO; j++) {
            float x = h3b[j];
#pragma unroll
            for (int cc = 0; cc < NC; cc++) acc[cc] = fmaf(Wsw[cc * 304 + 252 + j], x, acc[cc]);
        }
    }

    float m = acc[0];
#pragma unroll
    for (int cc = 1; cc < NC; cc++) m = fmaxf(m, acc[cc]);
    float s = 0.0f;
#pragma unroll
    for (int cc = 0; cc < NC; cc++) s += __expf(acc[cc] - m);
    float lse = m + logf(s);
#pragma unroll
    for (int cc = 0; cc < NC; cc++) out[(size_t)t * NC + cc] = acc[cc] - lse;
}

// ---------------- launcher (single stream, fully serial-safe) ----------------
extern "C" void kernel_launch(void* const* d_in, const int* in_sizes, int n_in,
                              void* d_out, int out_size) {
    const float* U     = (const float*)d_in[0];
    const float* mask  = (const float*)d_in[1];
    const float* V     = (const float*)d_in[2];
    const float* Ww    = (const float*)d_in[3];
    const float* Wb    = (const float*)d_in[4];
    const float* Wsw   = (const float*)d_in[5];
    const float* Wsb   = (const float*)d_in[6];
    const float* Wih   = (const float*)d_in[7];
    const float* Whh   = (const float*)d_in[8];
    const float* bih   = (const float*)d_in[9];
    const float* bhh   = (const float*)d_in[10];
    const float* convw = (const float*)d_in[11];
    const float* convb = (const float*)d_in[12];
    float* out = (float*)d_out;

    const int smem2 = (MB * VS + 2 * CHELEMS + MB * D_SZ) * (int)sizeof(float)
                    + NCHUNKS * (int)sizeof(int);   // ~45.7 KB

    static bool attr_set = false;
    if (!attr_set) {
        cudaFuncSetAttribute(k23_fused, cudaFuncAttributeMaxDynamicSharedMemorySize, smem2);
        attr_set = true;
    }

    k_init<<<1, 32>>>();
    k0_fill<<<2048, 256>>>(V, Ww);
    k1_len<<<1, 1024>>>(mask, in_sizes[1]);
    k23_fused<<<NPROD + 1, NTHR, smem2>>>(U, Wb, Wih, bih, bhh, convw, convb, Whh);
    k4_epilogue<<<32, 128>>>(Wsw, Wsb, out);
}